// round 8
// baseline (speedup 1.0000x reference)
#include <cuda_runtime.h>
#include <cstdint>

// ---------------------------------------------------------------------------
// CharLSTM  (B=512, T=512, VOCAB=256, EMB=32, HID=128)
//
//   k_prep : blocks 0..255 -> embW[v][hcol] = emb[v]@W_ih^T + b_ih + b_hh
//            block 256     -> int64-vs-int32 input detection
//   k_lstm : 128 persistent CTAs x 4 batch rows x 512 steps, 512 threads
//            (4 warps/SMSP). Thread = (hcol, row j).
//            W_hh split: k4[0,26) in smem (208KB);
//            tail k4[26,32) DISTRIBUTED: thread (hcol,j) holds gate j's tail
//            (24 regs), computes partials for all 4 rows, 4x4 transpose via
//            padded smem scratch + __syncwarp.  ONE barrier per step.
// ---------------------------------------------------------------------------

#define VOCAB 256
#define EMB   32
#define HID   128
#define G4    512
#define BATCH 512
#define TLEN  512

#define NBLK  128
#define RPB   4
#define NTHR  512

#define K4S   26          // 4-k chunks in smem   (k 0..103)
#define K4T   6           // 4-k tail chunks in distributed regs (k 104..127)

// smem layout (bytes)
#define WS_BYTES   (K4S * G4 * 16)     // 212992
#define HB_BYTES   (2 * G4 * 4)        // 4096   h double buffer
#define TOK_BYTES  (RPB * TLEN * 2)    // 4096   uint16 tokens
#define SCR_BYTES  (HID * 20 * 4)      // 10240  tail-exchange scratch (padded)
#define SMEM_BYTES (WS_BYTES + HB_BYTES + TOK_BYTES + SCR_BYTES)  // 231424

__device__ int    g_is64;
__device__ float4 g_embW[VOCAB * HID];   // [v][hcol] = (i,f,g,o) addend

// ---- f32x2 helpers --------------------------------------------------------
__device__ __forceinline__ unsigned long long ffma2(unsigned long long a,
                                                    unsigned long long b,
                                                    unsigned long long c) {
    unsigned long long d;
    asm("fma.rn.f32x2 %0, %1, %2, %3;" : "=l"(d) : "l"(a), "l"(b), "l"(c));
    return d;
}
__device__ __forceinline__ float lo32(unsigned long long v) {
    return __uint_as_float((unsigned int)v);
}
__device__ __forceinline__ float hi32(unsigned long long v) {
    return __uint_as_float((unsigned int)(v >> 32));
}

// ---- activations (EX2/RCP based, ~2 ulp) ----------------------------------
__device__ __forceinline__ float sigf(float x) {
    return __fdividef(1.0f, 1.0f + __expf(-x));
}
__device__ __forceinline__ float tanhf_fast(float x) {
    return 1.0f - __fdividef(2.0f, __expf(2.0f * x) + 1.0f);
}

// ---------------------------------------------------------------------------
// Prep kernel: embW table (blocks 0..255) + input dtype detect (block 256)
// ---------------------------------------------------------------------------
__global__ void k_prep(const unsigned int* __restrict__ words,
                       const float* __restrict__ emb,
                       const float* __restrict__ W_ih,
                       const float* __restrict__ b_a,
                       const float* __restrict__ b_b) {
    if (blockIdx.x == VOCAB) {
        __shared__ int bad;
        if (threadIdx.x == 0) bad = 0;
        __syncthreads();
        int my = 0;
        for (int i = threadIdx.x; i < 4096; i += 128)
            if (words[2 * i + 1] != 0u) my = 1;
        if (my) bad = 1;
        __syncthreads();
        if (threadIdx.x == 0) g_is64 = bad ? 0 : 1;
        return;
    }
    __shared__ float e_s[EMB];
    int v  = blockIdx.x;
    int hc = threadIdx.x;
    if (threadIdx.x < EMB) e_s[threadIdx.x] = emb[v * EMB + threadIdx.x];
    __syncthreads();
    float acc[4];
#pragma unroll
    for (int q = 0; q < 4; q++) {
        int g = q * HID + hc;
        float s = b_a[g] + b_b[g];
        const float* wr = W_ih + g * EMB;
#pragma unroll
        for (int e = 0; e < EMB; e++) s += wr[e] * e_s[e];
        acc[q] = s;
    }
    g_embW[v * HID + hc] = make_float4(acc[0], acc[1], acc[2], acc[3]);
}

// ---------------------------------------------------------------------------
// Main persistent LSTM + classifier
// ---------------------------------------------------------------------------
extern __shared__ unsigned char smem_raw[];

__global__ void __launch_bounds__(NTHR, 1)
k_lstm(const void* __restrict__ inputs,
       const float* __restrict__ W_hh,
       const float* __restrict__ W_cls,
       const float* __restrict__ b_cls,
       float* __restrict__ out) {

    // wS[k4][gate*128 + hcol] : 16B chunk = W[gate*128+hcol][4k4 .. 4k4+3]
    ulonglong2*     wS  = (ulonglong2*)smem_raw;
    // h buffers: float idx = buf*512 + (hcol>>2)*16 + r*4 + (hcol&3)
    float*          hbF = (float*)(smem_raw + WS_BYTES);
    unsigned short* tok = (unsigned short*)(smem_raw + WS_BYTES + HB_BYTES);
    // tail scratch: scr[hcol*20 + gate*4 + row]  (stride 20 floats -> 8 hcols
    // of a warp land on 8 distinct bank groups -> conflict-free reads)
    float*          scr = (float*)(smem_raw + WS_BYTES + HB_BYTES + TOK_BYTES);

    const int tid   = threadIdx.x;
    const int rbase = blockIdx.x * RPB;
    const int hcol  = tid >> 2;      // 0..127
    const int j     = tid & 3;       // my batch row AND my tail gate

    // ---- token slab (uint16) ----------------------------------------------
    const int is64 = g_is64;
    for (int i = tid; i < RPB * TLEN; i += NTHR) {
        int rr = i >> 9;
        int t  = i & (TLEN - 1);
        long long gi = (long long)(rbase + rr) * TLEN + t;
        int tk;
        if (is64) tk = (int)((const unsigned int*)inputs)[2 * gi];
        else      tk = ((const int*)inputs)[gi];
        tok[rr * TLEN + t] = (unsigned short)(tk & 255);
    }

    // ---- stage W_hh smem part (k4 0..25) ----------------------------------
    const ulonglong2* W4 = (const ulonglong2*)W_hh;   // [512 rows][32 chunks]
    for (int i = tid; i < K4S * G4; i += NTHR) {
        int k4 = i >> 9;
        int g  = i & 511;
        wS[k4 * G4 + g] = W4[g * 32 + k4];
    }

    // ---- distributed tail weights: gate j of this hcol, k4 26..31 ---------
    ulonglong2 wt[K4T];
    {
        const ulonglong2* p = W4 + (j * HID + hcol) * 32 + K4S;
#pragma unroll
        for (int k = 0; k < K4T; k++) wt[k] = p[k];
    }

    // ---- zero h buffer 0 ---------------------------------------------------
    for (int i = tid; i < G4; i += NTHR) hbF[i] = 0.0f;

    float c = 0.0f;
    __syncthreads();

    const unsigned short* tp = tok + j * TLEN;
    const ulonglong2* wp = wS + hcol;
    float* scrp = scr + hcol * 20;
    const int hwidx = (hcol >> 2) * 16 + j * 4 + (hcol & 3);

    // =========================== time loop ==================================
    for (int t = 0; t < TLEN; t++) {
        const int cur = t & 1;

        // epilogue addends (L2 table; latency hidden under GEMM)
        int tk = tp[t];
        float4 e = g_embW[tk * HID + hcol];

        const ulonglong2* hB = (const ulonglong2*)(hbF + cur * G4);

        // ---- tail: gate j, all 4 rows, k4 26..31 ---------------------------
        unsigned long long tp0 = 0, tp1 = 0, tp2 = 0, tp3 = 0;
#pragma unroll
        for (int k = 0; k < K4T; k++) {
            const ulonglong2* hb4 = hB + (K4S + k) * 4;
            ulonglong2 h0 = hb4[0], h1 = hb4[1], h2 = hb4[2], h3 = hb4[3];
            tp0 = ffma2(wt[k].x, h0.x, tp0);  tp0 = ffma2(wt[k].y, h0.y, tp0);
            tp1 = ffma2(wt[k].x, h1.x, tp1);  tp1 = ffma2(wt[k].y, h1.y, tp1);
            tp2 = ffma2(wt[k].x, h2.x, tp2);  tp2 = ffma2(wt[k].y, h2.y, tp2);
            tp3 = ffma2(wt[k].x, h3.x, tp3);  tp3 = ffma2(wt[k].y, h3.y, tp3);
        }
        // publish tail partials: scr[hcol*20 + j*4 + row]
        *(float4*)(scrp + j * 4) = make_float4(lo32(tp0) + hi32(tp0),
                                               lo32(tp1) + hi32(tp1),
                                               lo32(tp2) + hi32(tp2),
                                               lo32(tp3) + hi32(tp3));

        // ---- main GEMM: k4 0..25, own row, all 4 gates ---------------------
        unsigned long long a0 = 0, a1 = 0, a2 = 0, a3 = 0;
#pragma unroll 13
        for (int k4 = 0; k4 < K4S; k4++) {
            ulonglong2 hx = hB[k4 * 4 + j];            // h[4k4..4k4+3][row j]
            ulonglong2 w0 = wp[k4 * G4 + 0 * HID];
            ulonglong2 w1 = wp[k4 * G4 + 1 * HID];
            ulonglong2 w2 = wp[k4 * G4 + 2 * HID];
            ulonglong2 w3 = wp[k4 * G4 + 3 * HID];
            a0 = ffma2(w0.x, hx.x, a0);  a0 = ffma2(w0.y, hx.y, a0);
            a1 = ffma2(w1.x, hx.x, a1);  a1 = ffma2(w1.y, hx.y, a1);
            a2 = ffma2(w2.x, hx.x, a2);  a2 = ffma2(w2.y, hx.y, a2);
            a3 = ffma2(w3.x, hx.x, a3);  a3 = ffma2(w3.y, hx.y, a3);
        }

        // ---- gather tail partials for MY row from the 4 gate-lanes ---------
        __syncwarp();
        float g0 = scrp[0 * 4 + j];
        float g1 = scrp[1 * 4 + j];
        float g2 = scrp[2 * 4 + j];
        float g3 = scrp[3 * 4 + j];

        // ---- local epilogue ------------------------------------------------
        float ip = lo32(a0) + hi32(a0) + g0 + e.x;
        float fp = lo32(a1) + hi32(a1) + g1 + e.y;
        float gp = lo32(a2) + hi32(a2) + g2 + e.z;
        float op = lo32(a3) + hi32(a3) + g3 + e.w;
        float si = sigf(ip), sf = sigf(fp);
        float sg = tanhf_fast(gp), so = sigf(op);
        c = sf * c + si * sg;
        hbF[(cur ^ 1) * G4 + hwidx] = so * tanhf_fast(c);

        __syncthreads();   // h(next) + scratch safe before next step
    }

    // =========================== classifier =================================
    // final h in buffer 0. Linearize into tok area (reused as float[512]).
    float* hlin = (float*)tok;
    for (int i = tid; i < RPB * HID; i += NTHR) {
        int rr = i >> 7;
        int k  = i & (HID - 1);
        hlin[rr * HID + k] = hbF[(k >> 2) * 16 + rr * 4 + (k & 3)];
    }
    __syncthreads();

    {
        int v    = tid & 255;            // vocab column
        int half = tid >> 8;             // 0: rows 0,1   1: rows 2,3
        int ra   = 2 * half;
        float bb = b_cls[v];
        float accA = bb, accB = bb;
        const float4* wc = (const float4*)(W_cls + v * HID);
        const float4* hA = (const float4*)(hlin + ra * HID);
        const float4* hBp = (const float4*)(hlin + (ra + 1) * HID);
#pragma unroll 8
        for (int k4 = 0; k4 < HID / 4; k4++) {
            float4 w  = wc[k4];
            float4 va = hA[k4], vb = hBp[k4];
            accA += w.x * va.x + w.y * va.y + w.z * va.z + w.w * va.w;
            accB += w.x * vb.x + w.y * vb.y + w.z * vb.z + w.w * vb.w;
        }
        out[(rbase + ra) * VOCAB + v]     = accA;
        out[(rbase + ra + 1) * VOCAB + v] = accB;
    }
}

// ---------------------------------------------------------------------------
// Host launcher (inputs mapped by element count; bias ambiguity harmless:
// biases only ever used summed).
// ---------------------------------------------------------------------------
extern "C" void kernel_launch(void* const* d_in, const int* in_sizes, int n_in,
                              void* d_out, int out_size) {
    const void*  inputs = nullptr;
    const float* emb = nullptr;
    const float* W_ih = nullptr;
    const float* W_hh = nullptr;
    const float* b_a = nullptr;
    const float* b_b = nullptr;
    const float* W_cls = nullptr;
    const float* b_cls = nullptr;

    for (int i = 0; i < n_in; i++) {
        int sz = in_sizes[i];
        const void* p = d_in[i];
        switch (sz) {
            case BATCH * TLEN:   inputs = p;                 break;
            case VOCAB * EMB:    emb    = (const float*)p;   break;
            case G4 * EMB:       W_ih   = (const float*)p;   break;
            case G4 * HID:       W_hh   = (const float*)p;   break;
            case VOCAB * HID:    W_cls  = (const float*)p;   break;
            case VOCAB:          b_cls  = (const float*)p;   break;
            case G4:
                if (!b_a) b_a = (const float*)p; else b_b = (const float*)p;
                break;
            default: break;
        }
    }
    if (!inputs || !emb || !W_ih || !W_hh || !b_a || !b_b || !W_cls || !b_cls)
        return;

    cudaFuncSetAttribute(k_lstm, cudaFuncAttributeMaxDynamicSharedMemorySize,
                         SMEM_BYTES);

    k_prep<<<VOCAB + 1, 128>>>((const unsigned int*)inputs, emb, W_ih, b_a, b_b);
    k_lstm<<<NBLK, NTHR, SMEM_BYTES>>>(inputs, W_hh, W_cls, b_cls,
                                       (float*)d_out);
}

// round 9
// speedup vs baseline: 1.7713x; 1.7713x over previous
#include <cuda_runtime.h>
#include <cstdint>

// ---------------------------------------------------------------------------
// CharLSTM  (B=512, T=512, VOCAB=256, EMB=32, HID=128)
//
//   k_prep : blocks 0..255 -> embW[v][hcol] = emb[v]@W_ih^T + b_ih + b_hh
//            block 256     -> int64-vs-int32 input detection
//   k_lstm : 128 persistent CTAs x 4 batch rows x 512 steps, 256 threads.
//            Thread = (hcol, rowpair). Computes ALL 4 gate preacts for its
//            own 2 epilogue items (8 f32x2 accumulators) -> ZERO gate
//            exchange, ONE barrier/step. W_hh: k4[0,27) smem (221KB,
//            permuted [k4][gate][hcol]), k4[27,32) in regs (80 regs; fits
//            easily under the 256-reg/thread cap at 256 threads -> NO SPILL).
// ---------------------------------------------------------------------------

#define VOCAB 256
#define EMB   32
#define HID   128
#define G4    512
#define BATCH 512
#define TLEN  512

#define NBLK  128
#define RPB   4
#define NTHR  256

#define K4S   27          // 4-k chunks in smem   (k 0..107)
#define K4T   5           // 4-k chunks in regs   (k 108..127)

// smem layout (bytes)
#define WS_BYTES   (K4S * G4 * 16)     // 221184  weights [k4][gate][hcol] ull2
#define HB_BYTES   (2 * G4 * 4)        // 4096    h double buffer
#define TOK_BYTES  (RPB * TLEN * 2)    // 4096    uint16 tokens
#define SMEM_BYTES (WS_BYTES + HB_BYTES + TOK_BYTES)   // 229376 <= 232448

__device__ int    g_is64;
__device__ float4 g_embW[VOCAB * HID];   // [v][hcol] = (i,f,g,o) addend

// ---- f32x2 helpers --------------------------------------------------------
__device__ __forceinline__ unsigned long long ffma2(unsigned long long a,
                                                    unsigned long long b,
                                                    unsigned long long c) {
    unsigned long long d;
    asm("fma.rn.f32x2 %0, %1, %2, %3;" : "=l"(d) : "l"(a), "l"(b), "l"(c));
    return d;
}
__device__ __forceinline__ float lo32(unsigned long long v) {
    return __uint_as_float((unsigned int)v);
}
__device__ __forceinline__ float hi32(unsigned long long v) {
    return __uint_as_float((unsigned int)(v >> 32));
}

// ---- activations (EX2/RCP based, ~2 ulp) ----------------------------------
__device__ __forceinline__ float sigf(float x) {
    return __fdividef(1.0f, 1.0f + __expf(-x));
}
__device__ __forceinline__ float tanhf_fast(float x) {
    return 1.0f - __fdividef(2.0f, __expf(2.0f * x) + 1.0f);
}

// ---------------------------------------------------------------------------
// Prep kernel: embW table (blocks 0..255) + input dtype detect (block 256)
// ---------------------------------------------------------------------------
__global__ void k_prep(const unsigned int* __restrict__ words,
                       const float* __restrict__ emb,
                       const float* __restrict__ W_ih,
                       const float* __restrict__ b_a,
                       const float* __restrict__ b_b) {
    if (blockIdx.x == VOCAB) {
        __shared__ int bad;
        if (threadIdx.x == 0) bad = 0;
        __syncthreads();
        int my = 0;
        for (int i = threadIdx.x; i < 4096; i += 128)
            if (words[2 * i + 1] != 0u) my = 1;
        if (my) bad = 1;
        __syncthreads();
        if (threadIdx.x == 0) g_is64 = bad ? 0 : 1;
        return;
    }
    __shared__ float e_s[EMB];
    int v  = blockIdx.x;
    int hc = threadIdx.x;
    if (threadIdx.x < EMB) e_s[threadIdx.x] = emb[v * EMB + threadIdx.x];
    __syncthreads();
    float acc[4];
#pragma unroll
    for (int q = 0; q < 4; q++) {
        int g = q * HID + hc;
        float s = b_a[g] + b_b[g];
        const float* wr = W_ih + g * EMB;
#pragma unroll
        for (int e = 0; e < EMB; e++) s += wr[e] * e_s[e];
        acc[q] = s;
    }
    g_embW[v * HID + hc] = make_float4(acc[0], acc[1], acc[2], acc[3]);
}

// ---------------------------------------------------------------------------
// Main persistent LSTM + classifier
// ---------------------------------------------------------------------------
extern __shared__ unsigned char smem_raw[];

__global__ void __launch_bounds__(NTHR, 1)
k_lstm(const void* __restrict__ inputs,
       const float* __restrict__ W_hh,
       const float* __restrict__ W_cls,
       const float* __restrict__ b_cls,
       float* __restrict__ out) {

    // wS entry index = k4*512 + q*128 + hcol : ull2 = W[q*128+hcol][4k4..4k4+3]
    ulonglong2*     wS  = (ulonglong2*)smem_raw;
    // h buffers: float idx = buf*512 + k4*16 + r*4 + sub  (h[r][4k4+sub])
    float*          hbF = (float*)(smem_raw + WS_BYTES);
    unsigned short* tok = (unsigned short*)(smem_raw + WS_BYTES + HB_BYTES);

    const int tid   = threadIdx.x;
    const int rbase = blockIdx.x * RPB;
    const int hcol  = tid >> 1;      // 0..127
    const int rp    = tid & 1;       // row pair: rows {2rp, 2rp+1}
    const int r0    = 2 * rp;
    const int r1    = r0 + 1;

    // ---- token slab (uint16) ----------------------------------------------
    const int is64 = g_is64;
    for (int i = tid; i < RPB * TLEN; i += NTHR) {
        int rr = i >> 9;
        int t  = i & (TLEN - 1);
        long long gi = (long long)(rbase + rr) * TLEN + t;
        int tk;
        if (is64) tk = (int)((const unsigned int*)inputs)[2 * gi];
        else      tk = ((const int*)inputs)[gi];
        tok[rr * TLEN + t] = (unsigned short)(tk & 255);
    }

    // ---- stage W_hh smem part, permuted [k4][gate][hcol] ------------------
    const ulonglong2* W4 = (const ulonglong2*)W_hh;   // [512 rows][32 chunks]
    for (int i = tid; i < K4S * G4; i += NTHR) {
        int hc = i & 127;
        int q  = (i >> 7) & 3;
        int k4 = i >> 9;
        wS[i] = W4[(q * HID + hc) * 32 + k4];
    }

    // ---- register tail: k4 27..31, all 4 gates of this hcol (80 regs) -----
    ulonglong2 wt[4][K4T];
#pragma unroll
    for (int q = 0; q < 4; q++) {
        const ulonglong2* p = W4 + (q * HID + hcol) * 32 + K4S;
#pragma unroll
        for (int j = 0; j < K4T; j++) wt[q][j] = p[j];
    }

    // ---- zero h buffer 0 ---------------------------------------------------
    for (int i = tid; i < G4; i += NTHR) hbF[i] = 0.0f;

    float c0 = 0.0f, c1 = 0.0f;
    __syncthreads();

    const unsigned short* tpa = tok + r0 * TLEN;
    const unsigned short* tpb = tok + r1 * TLEN;
    const ulonglong2* wp = wS + hcol;
    const int hwbase = (hcol >> 2) * 16 + (hcol & 3);

    // =========================== time loop ==================================
    for (int t = 0; t < TLEN; t++) {
        const int cur = t & 1;

        // epilogue addends (hot-L2 table; issued early, hidden under GEMM)
        float4 e0 = g_embW[(int)tpa[t] * HID + hcol];
        float4 e1 = g_embW[(int)tpb[t] * HID + hcol];

        const float* hcur = hbF + cur * G4;

        unsigned long long a00 = 0, a01 = 0;   // gate i, rows r0,r1
        unsigned long long a10 = 0, a11 = 0;   // gate f
        unsigned long long a20 = 0, a21 = 0;   // gate g
        unsigned long long a30 = 0, a31 = 0;   // gate o

        // ---- smem weight part: k4 0..26 ------------------------------------
#pragma unroll
        for (int k4 = 0; k4 < K4S; k4++) {
            ulonglong2 h0 = *(const ulonglong2*)(hcur + k4 * 16 + r0 * 4);
            ulonglong2 h1 = *(const ulonglong2*)(hcur + k4 * 16 + r1 * 4);
            ulonglong2 w0 = wp[k4 * G4 + 0 * HID];
            ulonglong2 w1 = wp[k4 * G4 + 1 * HID];
            ulonglong2 w2 = wp[k4 * G4 + 2 * HID];
            ulonglong2 w3 = wp[k4 * G4 + 3 * HID];
            a00 = ffma2(w0.x, h0.x, a00);  a00 = ffma2(w0.y, h0.y, a00);
            a01 = ffma2(w0.x, h1.x, a01);  a01 = ffma2(w0.y, h1.y, a01);
            a10 = ffma2(w1.x, h0.x, a10);  a10 = ffma2(w1.y, h0.y, a10);
            a11 = ffma2(w1.x, h1.x, a11);  a11 = ffma2(w1.y, h1.y, a11);
            a20 = ffma2(w2.x, h0.x, a20);  a20 = ffma2(w2.y, h0.y, a20);
            a21 = ffma2(w2.x, h1.x, a21);  a21 = ffma2(w2.y, h1.y, a21);
            a30 = ffma2(w3.x, h0.x, a30);  a30 = ffma2(w3.y, h0.y, a30);
            a31 = ffma2(w3.x, h1.x, a31);  a31 = ffma2(w3.y, h1.y, a31);
        }

        // ---- register tail: k4 27..31 --------------------------------------
#pragma unroll
        for (int j = 0; j < K4T; j++) {
            int k4 = K4S + j;
            ulonglong2 h0 = *(const ulonglong2*)(hcur + k4 * 16 + r0 * 4);
            ulonglong2 h1 = *(const ulonglong2*)(hcur + k4 * 16 + r1 * 4);
            a00 = ffma2(wt[0][j].x, h0.x, a00);  a00 = ffma2(wt[0][j].y, h0.y, a00);
            a01 = ffma2(wt[0][j].x, h1.x, a01);  a01 = ffma2(wt[0][j].y, h1.y, a01);
            a10 = ffma2(wt[1][j].x, h0.x, a10);  a10 = ffma2(wt[1][j].y, h0.y, a10);
            a11 = ffma2(wt[1][j].x, h1.x, a11);  a11 = ffma2(wt[1][j].y, h1.y, a11);
            a20 = ffma2(wt[2][j].x, h0.x, a20);  a20 = ffma2(wt[2][j].y, h0.y, a20);
            a21 = ffma2(wt[2][j].x, h1.x, a21);  a21 = ffma2(wt[2][j].y, h1.y, a21);
            a30 = ffma2(wt[3][j].x, h0.x, a30);  a30 = ffma2(wt[3][j].y, h0.y, a30);
            a31 = ffma2(wt[3][j].x, h1.x, a31);  a31 = ffma2(wt[3][j].y, h1.y, a31);
        }

        // ---- fully local epilogue: gates never leave this thread -----------
        float* hnext = hbF + (cur ^ 1) * G4 + hwbase;
        {
            float ip = lo32(a00) + hi32(a00) + e0.x;
            float fp = lo32(a10) + hi32(a10) + e0.y;
            float gp = lo32(a20) + hi32(a20) + e0.z;
            float op = lo32(a30) + hi32(a30) + e0.w;
            float si = sigf(ip), sf = sigf(fp);
            float sg = tanhf_fast(gp), so = sigf(op);
            c0 = sf * c0 + si * sg;
            hnext[r0 * 4] = so * tanhf_fast(c0);
        }
        {
            float ip = lo32(a01) + hi32(a01) + e1.x;
            float fp = lo32(a11) + hi32(a11) + e1.y;
            float gp = lo32(a21) + hi32(a21) + e1.z;
            float op = lo32(a31) + hi32(a31) + e1.w;
            float si = sigf(ip), sf = sigf(fp);
            float sg = tanhf_fast(gp), so = sigf(op);
            c1 = sf * c1 + si * sg;
            hnext[r1 * 4] = so * tanhf_fast(c1);
        }

        __syncthreads();   // the ONLY barrier: h(next) complete before reads
    }

    // =========================== classifier =================================
    // final h in buffer 0 (T even). Linearize into tok area (reused).
    float* hlin = (float*)tok;
    for (int i = tid; i < RPB * HID; i += NTHR) {
        int rr = i >> 7;
        int k  = i & (HID - 1);
        hlin[rr * HID + k] = hbF[(k >> 2) * 16 + rr * 4 + (k & 3)];
    }
    __syncthreads();

    {
        int v = tid;                                  // 0..255 vocab cols
        float bb = b_cls[v];
        float acc0 = bb, acc1 = bb, acc2 = bb, acc3 = bb;
        const float4* wc = (const float4*)(W_cls + v * HID);
        const float4* h0 = (const float4*)(hlin + 0 * HID);
        const float4* h1 = (const float4*)(hlin + 1 * HID);
        const float4* h2 = (const float4*)(hlin + 2 * HID);
        const float4* h3 = (const float4*)(hlin + 3 * HID);
#pragma unroll 8
        for (int k4 = 0; k4 < HID / 4; k4++) {
            float4 w  = wc[k4];
            float4 v0 = h0[k4], v1 = h1[k4], v2 = h2[k4], v3 = h3[k4];
            acc0 += w.x * v0.x + w.y * v0.y + w.z * v0.z + w.w * v0.w;
            acc1 += w.x * v1.x + w.y * v1.y + w.z * v1.z + w.w * v1.w;
            acc2 += w.x * v2.x + w.y * v2.y + w.z * v2.z + w.w * v2.w;
            acc3 += w.x * v3.x + w.y * v3.y + w.z * v3.z + w.w * v3.w;
        }
        out[(rbase + 0) * VOCAB + v] = acc0;
        out[(rbase + 1) * VOCAB + v] = acc1;
        out[(rbase + 2) * VOCAB + v] = acc2;
        out[(rbase + 3) * VOCAB + v] = acc3;
    }
}

// ---------------------------------------------------------------------------
// Host launcher (inputs mapped by element count; bias ambiguity harmless:
// biases only ever used summed).
// ---------------------------------------------------------------------------
extern "C" void kernel_launch(void* const* d_in, const int* in_sizes, int n_in,
                              void* d_out, int out_size) {
    const void*  inputs = nullptr;
    const float* emb = nullptr;
    const float* W_ih = nullptr;
    const float* W_hh = nullptr;
    const float* b_a = nullptr;
    const float* b_b = nullptr;
    const float* W_cls = nullptr;
    const float* b_cls = nullptr;

    for (int i = 0; i < n_in; i++) {
        int sz = in_sizes[i];
        const void* p = d_in[i];
        switch (sz) {
            case BATCH * TLEN:   inputs = p;                 break;
            case VOCAB * EMB:    emb    = (const float*)p;   break;
            case G4 * EMB:       W_ih   = (const float*)p;   break;
            case G4 * HID:       W_hh   = (const float*)p;   break;
            case VOCAB * HID:    W_cls  = (const float*)p;   break;
            case VOCAB:          b_cls  = (const float*)p;   break;
            case G4:
                if (!b_a) b_a = (const float*)p; else b_b = (const float*)p;
                break;
            default: break;
        }
    }
    if (!inputs || !emb || !W_ih || !W_hh || !b_a || !b_b || !W_cls || !b_cls)
        return;

    cudaFuncSetAttribute(k_lstm, cudaFuncAttributeMaxDynamicSharedMemorySize,
                         SMEM_BYTES);

    k_prep<<<VOCAB + 1, 128>>>((const unsigned int*)inputs, emb, W_ih, b_a, b_b);
    k_lstm<<<NBLK, NTHR, SMEM_BYTES>>>(inputs, W_hh, W_cls, b_cls,
                                       (float*)d_out);
}

// round 10
// speedup vs baseline: 1.8758x; 1.0590x over previous
#include <cuda_runtime.h>
#include <cstdint>

// ---------------------------------------------------------------------------
// CharLSTM  (B=512, T=512, VOCAB=256, EMB=32, HID=128)
//
//   k_prep : blocks 0..255 -> embW[v][hcol] = emb[v]@W_ih^T + b_ih + b_hh
//            block 256     -> int64-vs-int32 input detection
//   k_lstm : 128 persistent CTAs x 4 batch rows x 512 steps, 256 threads.
//            Thread = (hcol, rowpair), ALL 4 gate preacts local, ONE
//            barrier/step. W_hh: k4[0,26) smem (213KB, permuted
//            [k4][gate][hcol]), k4[26,32) in regs (96 regs).
//            Register tail issued FIRST each step (covers LDS ramp);
//            embW addends prefetched one step ahead.
// ---------------------------------------------------------------------------

#define VOCAB 256
#define EMB   32
#define HID   128
#define G4    512
#define BATCH 512
#define TLEN  512

#define NBLK  128
#define RPB   4
#define NTHR  256

#define K4S   26          // 4-k chunks in smem   (k 0..103)
#define K4T   6           // 4-k chunks in regs   (k 104..127)

// smem layout (bytes)
#define WS_BYTES   (K4S * G4 * 16)     // 212992  weights [k4][gate][hcol] ull2
#define HB_BYTES   (2 * G4 * 4)        // 4096    h double buffer
#define TOK_BYTES  (RPB * TLEN * 2)    // 4096    uint16 tokens
#define SMEM_BYTES (WS_BYTES + HB_BYTES + TOK_BYTES)   // 221184 <= 232448

__device__ int    g_is64;
__device__ float4 g_embW[VOCAB * HID];   // [v][hcol] = (i,f,g,o) addend

// ---- f32x2 helpers --------------------------------------------------------
__device__ __forceinline__ unsigned long long ffma2(unsigned long long a,
                                                    unsigned long long b,
                                                    unsigned long long c) {
    unsigned long long d;
    asm("fma.rn.f32x2 %0, %1, %2, %3;" : "=l"(d) : "l"(a), "l"(b), "l"(c));
    return d;
}
__device__ __forceinline__ float lo32(unsigned long long v) {
    return __uint_as_float((unsigned int)v);
}
__device__ __forceinline__ float hi32(unsigned long long v) {
    return __uint_as_float((unsigned int)(v >> 32));
}

// ---- activations (EX2/RCP based, ~2 ulp) ----------------------------------
__device__ __forceinline__ float sigf(float x) {
    return __fdividef(1.0f, 1.0f + __expf(-x));
}
__device__ __forceinline__ float tanhf_fast(float x) {
    return 1.0f - __fdividef(2.0f, __expf(2.0f * x) + 1.0f);
}

// ---------------------------------------------------------------------------
// Prep kernel: embW table (blocks 0..255) + input dtype detect (block 256)
// ---------------------------------------------------------------------------
__global__ void k_prep(const unsigned int* __restrict__ words,
                       const float* __restrict__ emb,
                       const float* __restrict__ W_ih,
                       const float* __restrict__ b_a,
                       const float* __restrict__ b_b) {
    if (blockIdx.x == VOCAB) {
        __shared__ int bad;
        if (threadIdx.x == 0) bad = 0;
        __syncthreads();
        int my = 0;
        for (int i = threadIdx.x; i < 4096; i += 128)
            if (words[2 * i + 1] != 0u) my = 1;
        if (my) bad = 1;
        __syncthreads();
        if (threadIdx.x == 0) g_is64 = bad ? 0 : 1;
        return;
    }
    __shared__ float e_s[EMB];
    int v  = blockIdx.x;
    int hc = threadIdx.x;
    if (threadIdx.x < EMB) e_s[threadIdx.x] = emb[v * EMB + threadIdx.x];
    __syncthreads();
    float acc[4];
#pragma unroll
    for (int q = 0; q < 4; q++) {
        int g = q * HID + hc;
        float s = b_a[g] + b_b[g];
        const float* wr = W_ih + g * EMB;
#pragma unroll
        for (int e = 0; e < EMB; e++) s += wr[e] * e_s[e];
        acc[q] = s;
    }
    g_embW[v * HID + hc] = make_float4(acc[0], acc[1], acc[2], acc[3]);
}

// ---------------------------------------------------------------------------
// Main persistent LSTM + classifier
// ---------------------------------------------------------------------------
extern __shared__ unsigned char smem_raw[];

__global__ void __launch_bounds__(NTHR, 1)
k_lstm(const void* __restrict__ inputs,
       const float* __restrict__ W_hh,
       const float* __restrict__ W_cls,
       const float* __restrict__ b_cls,
       float* __restrict__ out) {

    // wS entry index = k4*512 + q*128 + hcol : ull2 = W[q*128+hcol][4k4..4k4+3]
    ulonglong2*     wS  = (ulonglong2*)smem_raw;
    // h buffers: float idx = buf*512 + k4*16 + r*4 + sub  (h[r][4k4+sub])
    float*          hbF = (float*)(smem_raw + WS_BYTES);
    unsigned short* tok = (unsigned short*)(smem_raw + WS_BYTES + HB_BYTES);

    const int tid   = threadIdx.x;
    const int rbase = blockIdx.x * RPB;
    const int hcol  = tid >> 1;      // 0..127
    const int rp    = tid & 1;       // row pair: rows {2rp, 2rp+1}
    const int r0    = 2 * rp;
    const int r1    = r0 + 1;

    // ---- token slab (uint16) ----------------------------------------------
    const int is64 = g_is64;
    for (int i = tid; i < RPB * TLEN; i += NTHR) {
        int rr = i >> 9;
        int t  = i & (TLEN - 1);
        long long gi = (long long)(rbase + rr) * TLEN + t;
        int tk;
        if (is64) tk = (int)((const unsigned int*)inputs)[2 * gi];
        else      tk = ((const int*)inputs)[gi];
        tok[rr * TLEN + t] = (unsigned short)(tk & 255);
    }

    // ---- stage W_hh smem part, permuted [k4][gate][hcol] ------------------
    const ulonglong2* W4 = (const ulonglong2*)W_hh;   // [512 rows][32 chunks]
    for (int i = tid; i < K4S * G4; i += NTHR) {
        int hc = i & 127;
        int q  = (i >> 7) & 3;
        int k4 = i >> 9;
        wS[i] = W4[(q * HID + hc) * 32 + k4];
    }

    // ---- register tail: k4 26..31, all 4 gates of this hcol (96 regs) -----
    ulonglong2 wt[4][K4T];
#pragma unroll
    for (int q = 0; q < 4; q++) {
        const ulonglong2* p = W4 + (q * HID + hcol) * 32 + K4S;
#pragma unroll
        for (int j = 0; j < K4T; j++) wt[q][j] = p[j];
    }

    // ---- zero h buffer 0 ---------------------------------------------------
    for (int i = tid; i < G4; i += NTHR) hbF[i] = 0.0f;

    float c0 = 0.0f, c1 = 0.0f;
    __syncthreads();

    const unsigned short* tpa = tok + r0 * TLEN;
    const unsigned short* tpb = tok + r1 * TLEN;
    const ulonglong2* wp = wS + hcol;
    const int hwbase = (hcol >> 2) * 16 + (hcol & 3);

    // embW prefetch pipeline: e*n hold addends for step t (loaded 1 step early)
    float4 e0n = g_embW[(int)tpa[0] * HID + hcol];
    float4 e1n = g_embW[(int)tpb[0] * HID + hcol];

    // =========================== time loop ==================================
    for (int t = 0; t < TLEN; t++) {
        const int cur = t & 1;

        float4 e0 = e0n, e1 = e1n;
        // prefetch next step's addends (cover: entire GEMM + barrier)
        {
            int tn = (t + 1) & (TLEN - 1);
            e0n = g_embW[(int)tpa[tn] * HID + hcol];
            e1n = g_embW[(int)tpb[tn] * HID + hcol];
        }

        const float* hcur = hbF + cur * G4;

        unsigned long long a00 = 0, a01 = 0;   // gate i, rows r0,r1
        unsigned long long a10 = 0, a11 = 0;   // gate f
        unsigned long long a20 = 0, a21 = 0;   // gate g
        unsigned long long a30 = 0, a31 = 0;   // gate o

        // ---- register tail FIRST: k4 26..31 (fma-only, covers LDS ramp) ----
#pragma unroll
        for (int j = 0; j < K4T; j++) {
            int k4 = K4S + j;
            ulonglong2 h0 = *(const ulonglong2*)(hcur + k4 * 16 + r0 * 4);
            ulonglong2 h1 = *(const ulonglong2*)(hcur + k4 * 16 + r1 * 4);
            a00 = ffma2(wt[0][j].x, h0.x, a00);  a00 = ffma2(wt[0][j].y, h0.y, a00);
            a01 = ffma2(wt[0][j].x, h1.x, a01);  a01 = ffma2(wt[0][j].y, h1.y, a01);
            a10 = ffma2(wt[1][j].x, h0.x, a10);  a10 = ffma2(wt[1][j].y, h0.y, a10);
            a11 = ffma2(wt[1][j].x, h1.x, a11);  a11 = ffma2(wt[1][j].y, h1.y, a11);
            a20 = ffma2(wt[2][j].x, h0.x, a20);  a20 = ffma2(wt[2][j].y, h0.y, a20);
            a21 = ffma2(wt[2][j].x, h1.x, a21);  a21 = ffma2(wt[2][j].y, h1.y, a21);
            a30 = ffma2(wt[3][j].x, h0.x, a30);  a30 = ffma2(wt[3][j].y, h0.y, a30);
            a31 = ffma2(wt[3][j].x, h1.x, a31);  a31 = ffma2(wt[3][j].y, h1.y, a31);
        }

        // ---- smem weight part: k4 0..25 ------------------------------------
#pragma unroll
        for (int k4 = 0; k4 < K4S; k4++) {
            ulonglong2 h0 = *(const ulonglong2*)(hcur + k4 * 16 + r0 * 4);
            ulonglong2 h1 = *(const ulonglong2*)(hcur + k4 * 16 + r1 * 4);
            ulonglong2 w0 = wp[k4 * G4 + 0 * HID];
            ulonglong2 w1 = wp[k4 * G4 + 1 * HID];
            ulonglong2 w2 = wp[k4 * G4 + 2 * HID];
            ulonglong2 w3 = wp[k4 * G4 + 3 * HID];
            a00 = ffma2(w0.x, h0.x, a00);  a00 = ffma2(w0.y, h0.y, a00);
            a01 = ffma2(w0.x, h1.x, a01);  a01 = ffma2(w0.y, h1.y, a01);
            a10 = ffma2(w1.x, h0.x, a10);  a10 = ffma2(w1.y, h0.y, a10);
            a11 = ffma2(w1.x, h1.x, a11);  a11 = ffma2(w1.y, h1.y, a11);
            a20 = ffma2(w2.x, h0.x, a20);  a20 = ffma2(w2.y, h0.y, a20);
            a21 = ffma2(w2.x, h1.x, a21);  a21 = ffma2(w2.y, h1.y, a21);
            a30 = ffma2(w3.x, h0.x, a30);  a30 = ffma2(w3.y, h0.y, a30);
            a31 = ffma2(w3.x, h1.x, a31);  a31 = ffma2(w3.y, h1.y, a31);
        }

        // ---- fully local epilogue: gates never leave this thread -----------
        float* hnext = hbF + (cur ^ 1) * G4 + hwbase;
        {
            float ip = lo32(a00) + hi32(a00) + e0.x;
            float fp = lo32(a10) + hi32(a10) + e0.y;
            float gp = lo32(a20) + hi32(a20) + e0.z;
            float op = lo32(a30) + hi32(a30) + e0.w;
            float si = sigf(ip), sf = sigf(fp);
            float sg = tanhf_fast(gp), so = sigf(op);
            c0 = sf * c0 + si * sg;
            hnext[r0 * 4] = so * tanhf_fast(c0);
        }
        {
            float ip = lo32(a01) + hi32(a01) + e1.x;
            float fp = lo32(a11) + hi32(a11) + e1.y;
            float gp = lo32(a21) + hi32(a21) + e1.z;
            float op = lo32(a31) + hi32(a31) + e1.w;
            float si = sigf(ip), sf = sigf(fp);
            float sg = tanhf_fast(gp), so = sigf(op);
            c1 = sf * c1 + si * sg;
            hnext[r1 * 4] = so * tanhf_fast(c1);
        }

        __syncthreads();   // the ONLY barrier: h(next) complete before reads
    }

    // =========================== classifier =================================
    // final h in buffer 0 (T even). Linearize into tok area (reused).
    float* hlin = (float*)tok;
    for (int i = tid; i < RPB * HID; i += NTHR) {
        int rr = i >> 7;
        int k  = i & (HID - 1);
        hlin[rr * HID + k] = hbF[(k >> 2) * 16 + rr * 4 + (k & 3)];
    }
    __syncthreads();

    {
        int v = tid;                                  // 0..255 vocab cols
        float bb = b_cls[v];
        float acc0 = bb, acc1 = bb, acc2 = bb, acc3 = bb;
        const float4* wc = (const float4*)(W_cls + v * HID);
        const float4* h0 = (const float4*)(hlin + 0 * HID);
        const float4* h1 = (const float4*)(hlin + 1 * HID);
        const float4* h2 = (const float4*)(hlin + 2 * HID);
        const float4* h3 = (const float4*)(hlin + 3 * HID);
#pragma unroll 8
        for (int k4 = 0; k4 < HID / 4; k4++) {
            float4 w  = wc[k4];
            float4 v0 = h0[k4], v1 = h1[k4], v2 = h2[k4], v3 = h3[k4];
            acc0 += w.x * v0.x + w.y * v0.y + w.z * v0.z + w.w * v0.w;
            acc1 += w.x * v1.x + w.y * v1.y + w.z * v1.z + w.w * v1.w;
            acc2 += w.x * v2.x + w.y * v2.y + w.z * v2.z + w.w * v2.w;
            acc3 += w.x * v3.x + w.y * v3.y + w.z * v3.z + w.w * v3.w;
        }
        out[(rbase + 0) * VOCAB + v] = acc0;
        out[(rbase + 1) * VOCAB + v] = acc1;
        out[(rbase + 2) * VOCAB + v] = acc2;
        out[(rbase + 3) * VOCAB + v] = acc3;
    }
}

// ---------------------------------------------------------------------------
// Host launcher (inputs mapped by element count; bias ambiguity harmless:
// biases only ever used summed).
// ---------------------------------------------------------------------------
extern "C" void kernel_launch(void* const* d_in, const int* in_sizes, int n_in,
                              void* d_out, int out_size) {
    const void*  inputs = nullptr;
    const float* emb = nullptr;
    const float* W_ih = nullptr;
    const float* W_hh = nullptr;
    const float* b_a = nullptr;
    const float* b_b = nullptr;
    const float* W_cls = nullptr;
    const float* b_cls = nullptr;

    for (int i = 0; i < n_in; i++) {
        int sz = in_sizes[i];
        const void* p = d_in[i];
        switch (sz) {
            case BATCH * TLEN:   inputs = p;                 break;
            case VOCAB * EMB:    emb    = (const float*)p;   break;
            case G4 * EMB:       W_ih   = (const float*)p;   break;
            case G4 * HID:       W_hh   = (const float*)p;   break;
            case VOCAB * HID:    W_cls  = (const float*)p;   break;
            case VOCAB:          b_cls  = (const float*)p;   break;
            case G4:
                if (!b_a) b_a = (const float*)p; else b_b = (const float*)p;
                break;
            default: break;
        }
    }
    if (!inputs || !emb || !W_ih || !W_hh || !b_a || !b_b || !W_cls || !b_cls)
        return;

    cudaFuncSetAttribute(k_lstm, cudaFuncAttributeMaxDynamicSharedMemorySize,
                         SMEM_BYTES);

    k_prep<<<VOCAB + 1, 128>>>((const unsigned int*)inputs, emb, W_ih, b_a, b_b);
    k_lstm<<<NBLK, NTHR, SMEM_BYTES>>>(inputs, W_hh, W_cls, b_cls,
                                       (float*)d_out);
}